// round 11
// baseline (speedup 1.0000x reference)
#include <cuda_runtime.h>
#include <cuda_bf16.h>
#include <math_constants.h>
#include <cstdint>

// Causal attention B=4 L=4096 D=128 fp32 via mma.sync bf16 hi/lo split (3-term).
// Pass 1: convert Q/K/V fp32 -> bf16 hi + bf16 lo (Q pre-scaled by 1/sqrt(128)).
// Pass 2: FA2, BQ=128 x BK=64, 256 threads = 8 warps; warp w owns q-rows
// [16w,16w+16) -> softmax fully warp-local. K/V double-buffered via cp.async.
// CTA p handles q-tiles p and 31-p: exactly 66 k-tile iterations per CTA.

namespace {
constexpr int SEQ = 4096, HD = 128, NB = 4;
constexpr int BQ = 128, BK = 64;
constexpr int NQT = SEQ / BQ;  // 32
constexpr int NTH = 256;
constexpr size_t TELEM = (size_t)NB * SEQ * HD;

// smem: Q hi/lo 64KB, then two 64KB K/V buffers (KH,KL,VH,VL each 16KB).
constexpr int SM_QH = 0, SM_QL = 32768;
constexpr int SM_BUF0 = 65536;
constexpr int BUF_STRIDE = 65536;
constexpr int SMEM_BYTES = SM_BUF0 + 2 * BUF_STRIDE;  // 196608
}  // namespace

__device__ __nv_bfloat16 g_hi[3][TELEM];  // 0=K, 1=Q(scaled), 2=V
__device__ __nv_bfloat16 g_lo[3][TELEM];

namespace {

__device__ __forceinline__ unsigned smem_u32(const void* p) {
  unsigned a;
  asm("{ .reg .u64 t; cvta.to.shared.u64 t, %1; cvt.u32.u64 %0, t; }" : "=r"(a) : "l"(p));
  return a;
}

__device__ __forceinline__ void splitpk(float x, float y, unsigned& hi, unsigned& lo) {
  __nv_bfloat162 h = __floats2bfloat162_rn(x, y);
  hi = *reinterpret_cast<unsigned*>(&h);
  __nv_bfloat162 l = __floats2bfloat162_rn(x - __bfloat162float(h.x),
                                           y - __bfloat162float(h.y));
  lo = *reinterpret_cast<unsigned*>(&l);
}

__device__ __forceinline__ void ldsm4(unsigned* r, unsigned a) {
  asm volatile("ldmatrix.sync.aligned.m8n8.x4.shared.b16 {%0,%1,%2,%3}, [%4];"
               : "=r"(r[0]), "=r"(r[1]), "=r"(r[2]), "=r"(r[3]) : "r"(a));
}

__device__ __forceinline__ void ldsm4t(unsigned* r, unsigned a) {
  asm volatile("ldmatrix.sync.aligned.m8n8.x4.trans.shared.b16 {%0,%1,%2,%3}, [%4];"
               : "=r"(r[0]), "=r"(r[1]), "=r"(r[2]), "=r"(r[3]) : "r"(a));
}

__device__ __forceinline__ void mma16816(float* d, const unsigned* a, unsigned b0,
                                         unsigned b1) {
  asm volatile(
      "mma.sync.aligned.m16n8k16.row.col.f32.bf16.bf16.f32 "
      "{%0,%1,%2,%3}, {%4,%5,%6,%7}, {%8,%9}, {%0,%1,%2,%3};"
      : "+f"(d[0]), "+f"(d[1]), "+f"(d[2]), "+f"(d[3])
      : "r"(a[0]), "r"(a[1]), "r"(a[2]), "r"(a[3]), "r"(b0), "r"(b1));
}

// Synchronous copy of a ROWS x 128 bf16 tile into swizzled smem (256 threads).
// Chunk = 16B (16 per row); smem addr = row*256 + ((chunk ^ (row&7)) << 4).
template <int ROWS>
__device__ __forceinline__ void copy_tileN(char* sm, int off, const __nv_bfloat16* g,
                                           int tid) {
  const uint4* g4 = (const uint4*)g;
#pragma unroll
  for (int it = 0; it < ROWS * 16 / NTH; ++it) {
    const int c16 = it * NTH + tid;
    const int row = c16 >> 4, c = c16 & 15;
    const uint4 v = g4[c16];
    *(uint4*)(sm + off + row * 256 + ((c ^ (row & 7)) << 4)) = v;
  }
}

// Async copy of a 64 x 128 bf16 tile into swizzled smem (256 threads).
__device__ __forceinline__ void copy_tile_async(unsigned dst, const __nv_bfloat16* g,
                                                int tid) {
  const uint4* g4 = (const uint4*)g;
#pragma unroll
  for (int it = 0; it < 4; ++it) {
    const int c16 = it * NTH + tid;
    const int row = c16 >> 4, c = c16 & 15;
    const unsigned a = dst + row * 256 + ((c ^ (row & 7)) << 4);
    asm volatile("cp.async.cg.shared.global [%0], [%1], 16;" :: "r"(a), "l"(g4 + c16)
                 : "memory");
  }
}
}  // namespace

// ---- Pass 1: fp32 -> bf16 hi/lo (Q scaled by 1/sqrt(HD)) ----
__global__ void cvt_kernel(const float* __restrict__ K, const float* __restrict__ Q,
                           const float* __restrict__ V) {
  constexpr int N4 = (int)(TELEM / 4);
  const int stride = gridDim.x * blockDim.x;
  const float qscale = 0.088388347648318447f;  // 1/sqrt(128)
  for (int idx = blockIdx.x * blockDim.x + threadIdx.x; idx < 3 * N4; idx += stride) {
    const int t = idx / N4, e = idx - t * N4;
    const float* src = (t == 0) ? K : ((t == 1) ? Q : V);
    float4 v = ((const float4*)src)[e];
    if (t == 1) {
      v.x *= qscale; v.y *= qscale; v.z *= qscale; v.w *= qscale;
    }
    unsigned h0, l0, h1, l1;
    splitpk(v.x, v.y, h0, l0);
    splitpk(v.z, v.w, h1, l1);
    ((uint2*)g_hi[t])[e] = make_uint2(h0, h1);
    ((uint2*)g_lo[t])[e] = make_uint2(l0, l1);
  }
}

// ---- Pass 2: flash attention ----
__global__ __launch_bounds__(NTH, 1)
void fa_mma_kernel(float* __restrict__ Og) {
  extern __shared__ char sm[];
  const unsigned smb = smem_u32(sm);
  const int tid = threadIdx.x, lane = tid & 31, w = tid >> 5;  // w in 0..7
  const int g = lane >> 3, l7 = lane & 7, quad = lane >> 2, qlane = lane & 3;
  const int pair = blockIdx.x, b = blockIdx.y;

  const __nv_bfloat16* Kh = g_hi[0] + (size_t)b * SEQ * HD;
  const __nv_bfloat16* Kl = g_lo[0] + (size_t)b * SEQ * HD;
  const __nv_bfloat16* Qh = g_hi[1] + (size_t)b * SEQ * HD;
  const __nv_bfloat16* Ql = g_lo[1] + (size_t)b * SEQ * HD;
  const __nv_bfloat16* Vh = g_hi[2] + (size_t)b * SEQ * HD;
  const __nv_bfloat16* Vl = g_lo[2] + (size_t)b * SEQ * HD;

  // ldmatrix per-lane row/chunk offsets
  const int rowAl = ((g & 1) << 3) + l7;         // A (Q): g1/g3 -> rows+8
  const int cAoff = g >> 1;                      //        g2/g3 -> k+8
  const int rowBl = (((g >> 1) & 1) << 3) + l7;  // B (K): g2/g3 -> rows(n)+8
  const int cBoff = g & 1;                       //        g1/g3 -> k+8
  const int rowVl = ((g & 1) << 3) + l7;         // V(trans): g1/g3 -> keys+8
  const int cVoff = g >> 1;                      //        g2/g3 -> d+8

  for (int half = 0; half < 2; ++half) {
    const int qt = half ? (NQT - 1 - pair) : pair;
    const int q0 = qt * BQ;
    const int nkt = 2 * qt + 2;  // 64-key tiles covering [0, q0+BQ)

    __syncthreads();  // prior half's readers fully done before smem reuse
    copy_tileN<128>(sm, SM_QH, Qh + (size_t)q0 * HD, tid);
    copy_tileN<128>(sm, SM_QL, Ql + (size_t)q0 * HD, tid);

    // prologue: async-load k-tile 0 into buffer 0
    unsigned buf = 0;
    {
      const unsigned nb = smb + SM_BUF0;
      copy_tile_async(nb, Kh, tid);
      copy_tile_async(nb + 16384u, Kl, tid);
      copy_tile_async(nb + 32768u, Vh, tid);
      copy_tile_async(nb + 49152u, Vl, tid);
      asm volatile("cp.async.commit_group;" ::: "memory");
    }

    float o[16][4];
#pragma unroll
    for (int n = 0; n < 16; ++n)
#pragma unroll
      for (int e = 0; e < 4; ++e) o[n][e] = 0.f;
    float m0 = -CUDART_INF_F, m1 = -CUDART_INF_F, l0 = 0.f, l1 = 0.f;

    for (int kt = 0; kt < nkt; ++kt) {
      asm volatile("cp.async.wait_group 0;" ::: "memory");
      __syncthreads();  // buffer data visible; all warps past last iter's reads

      if (kt + 1 < nkt) {  // prefetch next tile into the other buffer
        const unsigned nb = smb + SM_BUF0 + (buf ^ 1u) * (unsigned)BUF_STRIDE;
        const size_t nk = (size_t)(kt + 1) * BK * HD;
        copy_tile_async(nb, Kh + nk, tid);
        copy_tile_async(nb + 16384u, Kl + nk, tid);
        copy_tile_async(nb + 32768u, Vh + nk, tid);
        copy_tile_async(nb + 49152u, Vl + nk, tid);
        asm volatile("cp.async.commit_group;" ::: "memory");
      }
      const unsigned kb = smb + SM_BUF0 + buf * (unsigned)BUF_STRIDE;
      buf ^= 1u;

      // ---- S = Qh*Kh + Qh*Kl + Ql*Kh (Q pre-scaled) ----
      float s[8][4];
#pragma unroll
      for (int n = 0; n < 8; ++n)
#pragma unroll
        for (int e = 0; e < 4; ++e) s[n][e] = 0.f;

      const unsigned arow = smb + SM_QH + (unsigned)(16 * w + rowAl) * 256u;
#pragma unroll
      for (int ks = 0; ks < 8; ++ks) {
        unsigned ah[4], al[4];
        const unsigned ca = (unsigned)(((2 * ks + cAoff) ^ l7) << 4);
        ldsm4(ah, arow + ca);
        ldsm4(al, arow + 32768u + ca);
        const unsigned cb = (unsigned)(((2 * ks + cBoff) ^ l7) << 4);
#pragma unroll
        for (int t = 0; t < 4; ++t) {
          unsigned bh[4], bl[4];
          const unsigned kaddr = kb + (unsigned)(t * 16 + rowBl) * 256u + cb;
          ldsm4(bh, kaddr);
          ldsm4(bl, kaddr + 16384u);
          // interleave the two accumulators: distance-2 dependency chains
          mma16816(s[2 * t], ah, bh[0], bh[1]);
          mma16816(s[2 * t + 1], ah, bh[2], bh[3]);
          mma16816(s[2 * t], ah, bl[0], bl[1]);
          mma16816(s[2 * t + 1], ah, bl[2], bl[3]);
          mma16816(s[2 * t], al, bh[0], bh[1]);
          mma16816(s[2 * t + 1], al, bh[2], bh[3]);
        }
      }

      // ---- causal mask: key offset within q-tile = (kt-2qt)*64 (last 2 tiles) ----
      if (kt >= 2 * qt) {
        const int off = (kt - 2 * qt) * 64;
        const int r0l = 16 * w + quad;
#pragma unroll
        for (int n = 0; n < 8; ++n) {
          const int c0 = off + 8 * n + 2 * qlane;
          if (c0 > r0l) s[n][0] = -CUDART_INF_F;
          if (c0 + 1 > r0l) s[n][1] = -CUDART_INF_F;
          if (c0 > r0l + 8) s[n][2] = -CUDART_INF_F;
          if (c0 + 1 > r0l + 8) s[n][3] = -CUDART_INF_F;
        }
      }

      // ---- online softmax (quad = the 4 lanes sharing a row; warp-local) ----
      float mx0 = -CUDART_INF_F, mx1 = -CUDART_INF_F;
#pragma unroll
      for (int n = 0; n < 8; ++n) {
        mx0 = fmaxf(mx0, fmaxf(s[n][0], s[n][1]));
        mx1 = fmaxf(mx1, fmaxf(s[n][2], s[n][3]));
      }
      mx0 = fmaxf(mx0, __shfl_xor_sync(0xffffffffu, mx0, 1));
      mx0 = fmaxf(mx0, __shfl_xor_sync(0xffffffffu, mx0, 2));
      mx1 = fmaxf(mx1, __shfl_xor_sync(0xffffffffu, mx1, 1));
      mx1 = fmaxf(mx1, __shfl_xor_sync(0xffffffffu, mx1, 2));
      const float m0n = fmaxf(m0, mx0), m1n = fmaxf(m1, mx1);
      const float a0 = __expf(m0 - m0n), a1 = __expf(m1 - m1n);
      float s0 = 0.f, s1 = 0.f;
#pragma unroll
      for (int n = 0; n < 8; ++n) {
        s[n][0] = __expf(s[n][0] - m0n);
        s[n][1] = __expf(s[n][1] - m0n);
        s[n][2] = __expf(s[n][2] - m1n);
        s[n][3] = __expf(s[n][3] - m1n);
        s0 += s[n][0] + s[n][1];
        s1 += s[n][2] + s[n][3];
      }
      s0 += __shfl_xor_sync(0xffffffffu, s0, 1);
      s0 += __shfl_xor_sync(0xffffffffu, s0, 2);
      s1 += __shfl_xor_sync(0xffffffffu, s1, 1);
      s1 += __shfl_xor_sync(0xffffffffu, s1, 2);
      l0 = l0 * a0 + s0;
      l1 = l1 * a1 + s1;
      m0 = m0n;
      m1 = m1n;

#pragma unroll
      for (int n = 0; n < 16; ++n) {
        o[n][0] *= a0;
        o[n][1] *= a0;
        o[n][2] *= a1;
        o[n][3] *= a1;
      }

      // ---- O += Ph*Vh + Ph*Vl + Pl*Vh ----
#pragma unroll
      for (int ks = 0; ks < 4; ++ks) {
        unsigned ah[4], al[4];
        splitpk(s[2 * ks][0], s[2 * ks][1], ah[0], al[0]);
        splitpk(s[2 * ks][2], s[2 * ks][3], ah[1], al[1]);
        splitpk(s[2 * ks + 1][0], s[2 * ks + 1][1], ah[2], al[2]);
        splitpk(s[2 * ks + 1][2], s[2 * ks + 1][3], ah[3], al[3]);
#pragma unroll
        for (int u = 0; u < 8; ++u) {
          unsigned vh[4], vl[4];
          const unsigned vaddr = kb + 32768u + (unsigned)(16 * ks + rowVl) * 256u +
                                 (unsigned)(((2 * u + cVoff) ^ l7) << 4);
          ldsm4t(vh, vaddr);
          ldsm4t(vl, vaddr + 16384u);
          mma16816(o[2 * u], ah, vh[0], vh[1]);
          mma16816(o[2 * u + 1], ah, vh[2], vh[3]);
          mma16816(o[2 * u], ah, vl[0], vl[1]);
          mma16816(o[2 * u + 1], ah, vl[2], vl[3]);
          mma16816(o[2 * u], al, vh[0], vh[1]);
          mma16816(o[2 * u + 1], al, vh[2], vh[3]);
        }
      }
    }  // kt

    // ---- epilogue ----
    const float i0 = 1.f / l0, i1 = 1.f / l1;
    const int r0 = q0 + 16 * w + quad;
    float* og = Og + ((size_t)b * SEQ + r0) * HD;
#pragma unroll
    for (int n = 0; n < 16; ++n) {
      const int col = 8 * n + 2 * qlane;
      *(float2*)(og + col) = make_float2(o[n][0] * i0, o[n][1] * i0);
      *(float2*)(og + 8 * HD + col) = make_float2(o[n][2] * i1, o[n][3] * i1);
    }
  }  // half
}

extern "C" void kernel_launch(void* const* d_in, const int* in_sizes, int n_in,
                              void* d_out, int out_size) {
  const float* K = (const float*)d_in[0];
  const float* Q = (const float*)d_in[1];
  const float* V = (const float*)d_in[2];
  float* O = (float*)d_out;

  cvt_kernel<<<2048, 256>>>(K, Q, V);

  cudaFuncSetAttribute(fa_mma_kernel, cudaFuncAttributeMaxDynamicSharedMemorySize,
                       SMEM_BYTES);
  dim3 grid(NQT / 2, NB);
  fa_mma_kernel<<<grid, NTH, SMEM_BYTES>>>(O);
}

// round 12
// speedup vs baseline: 1.8141x; 1.8141x over previous
#include <cuda_runtime.h>
#include <cuda_bf16.h>
#include <math_constants.h>
#include <cstdint>

// Causal attention B=4 L=4096 D=128 fp32 via mma.sync bf16 hi/lo split (3-term).
// Pass 1: cvt fp32 -> bf16 hi/lo (Q pre-scaled by 1/sqrt(128)).
// Pass 2: FA2 split-K: each (b, q-tile) is split into chunks of <=16 k-tiles.
//   640 chunk-CTAs (sizes descending for LPT balance), 4 warps, 96KB smem ->
//   2 CTAs/SM co-resident; K/V loaded with batched cp.async (single buffer).
//   Each chunk writes unnormalized partial O + (m, l) to global scratch.
// Pass 3: combine kernel merges <=4 partials per row (flash-decoding merge).

namespace {
constexpr int SEQ = 4096, HD = 128, NB = 4;
constexpr int BQ = 64, BK = 64;
constexpr int NTH = 128;
constexpr int CHUNK = 16;  // k-tiles per chunk
constexpr size_t TELEM = (size_t)NB * SEQ * HD;

// smem: Q hi/lo 32KB + single K/V buffer 64KB = 96KB (2 CTAs/SM)
constexpr int SM_QH = 0, SM_QL = 16384, SM_KH = 32768, SM_KL = 49152,
              SM_VH = 65536, SM_VL = 81920, SMEM_BYTES = 98304;

// chunks per q-tile: qt/16+1 (1..4). slots = (b*64+qt)*4 + c.
constexpr int NSLOT = NB * 64 * 4;  // 1024
}  // namespace

__device__ __nv_bfloat16 g_hi[3][TELEM];  // 0=K, 1=Q(scaled), 2=V
__device__ __nv_bfloat16 g_lo[3][TELEM];
__device__ float g_opart[NSLOT][BQ * HD];   // unnormalized partial O (34MB)
__device__ float2 g_mlpart[NSLOT][BQ];      // per-row (m, l)

namespace {

__device__ __forceinline__ unsigned smem_u32(const void* p) {
  unsigned a;
  asm("{ .reg .u64 t; cvta.to.shared.u64 t, %1; cvt.u32.u64 %0, t; }" : "=r"(a) : "l"(p));
  return a;
}

__device__ __forceinline__ void splitpk(float x, float y, unsigned& hi, unsigned& lo) {
  __nv_bfloat162 h = __floats2bfloat162_rn(x, y);
  hi = *reinterpret_cast<unsigned*>(&h);
  __nv_bfloat162 l = __floats2bfloat162_rn(x - __bfloat162float(h.x),
                                           y - __bfloat162float(h.y));
  lo = *reinterpret_cast<unsigned*>(&l);
}

__device__ __forceinline__ void ldsm4(unsigned* r, unsigned a) {
  asm volatile("ldmatrix.sync.aligned.m8n8.x4.shared.b16 {%0,%1,%2,%3}, [%4];"
               : "=r"(r[0]), "=r"(r[1]), "=r"(r[2]), "=r"(r[3]) : "r"(a));
}

__device__ __forceinline__ void ldsm4t(unsigned* r, unsigned a) {
  asm volatile("ldmatrix.sync.aligned.m8n8.x4.trans.shared.b16 {%0,%1,%2,%3}, [%4];"
               : "=r"(r[0]), "=r"(r[1]), "=r"(r[2]), "=r"(r[3]) : "r"(a));
}

__device__ __forceinline__ void mma16816(float* d, const unsigned* a, unsigned b0,
                                         unsigned b1) {
  asm volatile(
      "mma.sync.aligned.m16n8k16.row.col.f32.bf16.bf16.f32 "
      "{%0,%1,%2,%3}, {%4,%5,%6,%7}, {%8,%9}, {%0,%1,%2,%3};"
      : "+f"(d[0]), "+f"(d[1]), "+f"(d[2]), "+f"(d[3])
      : "r"(a[0]), "r"(a[1]), "r"(a[2]), "r"(a[3]), "r"(b0), "r"(b1));
}

// Synchronous copy of a 64x128 bf16 tile into swizzled smem (128 threads).
__device__ __forceinline__ void copy_tile(char* sm, int off, const __nv_bfloat16* g,
                                          int tid) {
  const uint4* g4 = (const uint4*)g;
#pragma unroll
  for (int it = 0; it < 8; ++it) {
    const int c16 = it * 128 + tid;
    const int row = c16 >> 4, c = c16 & 15;
    const uint4 v = g4[c16];
    *(uint4*)(sm + off + row * 256 + ((c ^ (row & 7)) << 4)) = v;
  }
}

// Async copy of a 64x128 bf16 tile into swizzled smem (128 threads).
__device__ __forceinline__ void copy_tile_async(unsigned dst, const __nv_bfloat16* g,
                                                int tid) {
  const uint4* g4 = (const uint4*)g;
#pragma unroll
  for (int it = 0; it < 8; ++it) {
    const int c16 = it * 128 + tid;
    const int row = c16 >> 4, c = c16 & 15;
    const unsigned a = dst + row * 256 + ((c ^ (row & 7)) << 4);
    asm volatile("cp.async.cg.shared.global [%0], [%1], 16;" :: "r"(a), "l"(g4 + c16)
                 : "memory");
  }
}
}  // namespace

// ---- Pass 1: fp32 -> bf16 hi/lo (Q scaled by 1/sqrt(HD)) ----
__global__ void cvt_kernel(const float* __restrict__ K, const float* __restrict__ Q,
                           const float* __restrict__ V) {
  constexpr int N4 = (int)(TELEM / 4);
  const int stride = gridDim.x * blockDim.x;
  const float qscale = 0.088388347648318447f;  // 1/sqrt(128)
  for (int idx = blockIdx.x * blockDim.x + threadIdx.x; idx < 3 * N4; idx += stride) {
    const int t = idx / N4, e = idx - t * N4;
    const float* src = (t == 0) ? K : ((t == 1) ? Q : V);
    float4 v = ((const float4*)src)[e];
    if (t == 1) {
      v.x *= qscale; v.y *= qscale; v.z *= qscale; v.w *= qscale;
    }
    unsigned h0, l0, h1, l1;
    splitpk(v.x, v.y, h0, l0);
    splitpk(v.z, v.w, h1, l1);
    ((uint2*)g_hi[t])[e] = make_uint2(h0, h1);
    ((uint2*)g_lo[t])[e] = make_uint2(l0, l1);
  }
}

// ---- Pass 2: flash attention chunk kernel ----
__global__ __launch_bounds__(NTH, 2)
void fa_mma_kernel() {
  extern __shared__ char sm[];
  const unsigned smb = smem_u32(sm);
  const int tid = threadIdx.x, lane = tid & 31, w = tid >> 5;
  const int g = lane >> 3, l7 = lane & 7, quad = lane >> 2, qlane = lane & 3;

  // decode chunk: batches interleaved, q-tiles descending (LPT order)
  const int b = blockIdx.x & 3;
  int ci = blockIdx.x >> 2;
  int qt = 0, c = 0;
  for (int t = 63; t >= 0; --t) {
    const int n = (t >> 4) + 1;
    if (ci < n) { qt = t; c = ci; break; }
    ci -= n;
  }
  const int q0 = qt * BQ;
  const int ktb = c * CHUNK;
  const int kte = min(ktb + CHUNK, qt + 1);

  const __nv_bfloat16* Kh = g_hi[0] + (size_t)b * SEQ * HD;
  const __nv_bfloat16* Kl = g_lo[0] + (size_t)b * SEQ * HD;
  const __nv_bfloat16* Qh = g_hi[1] + (size_t)b * SEQ * HD;
  const __nv_bfloat16* Ql = g_lo[1] + (size_t)b * SEQ * HD;
  const __nv_bfloat16* Vh = g_hi[2] + (size_t)b * SEQ * HD;
  const __nv_bfloat16* Vl = g_lo[2] + (size_t)b * SEQ * HD;

  // ldmatrix per-lane row/chunk offsets
  const int rowAl = ((g & 1) << 3) + l7;         // A (Q)
  const int cAoff = g >> 1;
  const int rowBl = (((g >> 1) & 1) << 3) + l7;  // B (K)
  const int cBoff = g & 1;
  const int rowVl = ((g & 1) << 3) + l7;         // V (trans)
  const int cVoff = g >> 1;

  copy_tile(sm, SM_QH, Qh + (size_t)q0 * HD, tid);
  copy_tile(sm, SM_QL, Ql + (size_t)q0 * HD, tid);

  // prologue: async-load first k-tile
  {
    const size_t nk = (size_t)ktb * BK * HD;
    copy_tile_async(smb + SM_KH, Kh + nk, tid);
    copy_tile_async(smb + SM_KL, Kl + nk, tid);
    copy_tile_async(smb + SM_VH, Vh + nk, tid);
    copy_tile_async(smb + SM_VL, Vl + nk, tid);
    asm volatile("cp.async.commit_group;" ::: "memory");
  }

  float o[16][4];
#pragma unroll
  for (int n = 0; n < 16; ++n)
#pragma unroll
    for (int e = 0; e < 4; ++e) o[n][e] = 0.f;
  float m0 = -CUDART_INF_F, m1 = -CUDART_INF_F, l0 = 0.f, l1 = 0.f;

  for (int kt = ktb; kt < kte; ++kt) {
    asm volatile("cp.async.wait_group 0;" ::: "memory");
    __syncthreads();  // buffer data visible to all warps

    // ---- S = Qh*Kh + Qh*Kl + Ql*Kh (Q pre-scaled) ----
    float s[8][4];
#pragma unroll
    for (int n = 0; n < 8; ++n)
#pragma unroll
      for (int e = 0; e < 4; ++e) s[n][e] = 0.f;

    const unsigned arow = smb + SM_QH + (unsigned)(16 * w + rowAl) * 256u;
#pragma unroll
    for (int ks = 0; ks < 8; ++ks) {
      unsigned ah[4], al[4];
      const unsigned ca = (unsigned)(((2 * ks + cAoff) ^ l7) << 4);
      ldsm4(ah, arow + ca);
      ldsm4(al, arow + 16384u + ca);
      const unsigned cb = (unsigned)(((2 * ks + cBoff) ^ l7) << 4);
#pragma unroll
      for (int t = 0; t < 4; ++t) {
        unsigned bh[4], bl[4];
        const unsigned kaddr = smb + SM_KH + (unsigned)(t * 16 + rowBl) * 256u + cb;
        ldsm4(bh, kaddr);
        ldsm4(bl, kaddr + 16384u);
        mma16816(s[2 * t], ah, bh[0], bh[1]);
        mma16816(s[2 * t + 1], ah, bh[2], bh[3]);
        mma16816(s[2 * t], ah, bl[0], bl[1]);
        mma16816(s[2 * t + 1], ah, bl[2], bl[3]);
        mma16816(s[2 * t], al, bh[0], bh[1]);
        mma16816(s[2 * t + 1], al, bh[2], bh[3]);
      }
    }

    // ---- causal mask on the diagonal tile ----
    if (kt == qt) {
      const int r0l = 16 * w + quad;
#pragma unroll
      for (int n = 0; n < 8; ++n) {
        const int c0 = 8 * n + 2 * qlane;
        if (c0 > r0l) s[n][0] = -CUDART_INF_F;
        if (c0 + 1 > r0l) s[n][1] = -CUDART_INF_F;
        if (c0 > r0l + 8) s[n][2] = -CUDART_INF_F;
        if (c0 + 1 > r0l + 8) s[n][3] = -CUDART_INF_F;
      }
    }

    // ---- online softmax (quad = 4 lanes sharing a row; warp-local) ----
    float mx0 = -CUDART_INF_F, mx1 = -CUDART_INF_F;
#pragma unroll
    for (int n = 0; n < 8; ++n) {
      mx0 = fmaxf(mx0, fmaxf(s[n][0], s[n][1]));
      mx1 = fmaxf(mx1, fmaxf(s[n][2], s[n][3]));
    }
    mx0 = fmaxf(mx0, __shfl_xor_sync(0xffffffffu, mx0, 1));
    mx0 = fmaxf(mx0, __shfl_xor_sync(0xffffffffu, mx0, 2));
    mx1 = fmaxf(mx1, __shfl_xor_sync(0xffffffffu, mx1, 1));
    mx1 = fmaxf(mx1, __shfl_xor_sync(0xffffffffu, mx1, 2));
    const float m0n = fmaxf(m0, mx0), m1n = fmaxf(m1, mx1);
    const float a0 = __expf(m0 - m0n), a1 = __expf(m1 - m1n);
    float s0 = 0.f, s1 = 0.f;
#pragma unroll
    for (int n = 0; n < 8; ++n) {
      s[n][0] = __expf(s[n][0] - m0n);
      s[n][1] = __expf(s[n][1] - m0n);
      s[n][2] = __expf(s[n][2] - m1n);
      s[n][3] = __expf(s[n][3] - m1n);
      s0 += s[n][0] + s[n][1];
      s1 += s[n][2] + s[n][3];
    }
    s0 += __shfl_xor_sync(0xffffffffu, s0, 1);
    s0 += __shfl_xor_sync(0xffffffffu, s0, 2);
    s1 += __shfl_xor_sync(0xffffffffu, s1, 1);
    s1 += __shfl_xor_sync(0xffffffffu, s1, 2);
    l0 = l0 * a0 + s0;
    l1 = l1 * a1 + s1;
    m0 = m0n;
    m1 = m1n;

#pragma unroll
    for (int n = 0; n < 16; ++n) {
      o[n][0] *= a0;
      o[n][1] *= a0;
      o[n][2] *= a1;
      o[n][3] *= a1;
    }

    // ---- O += Ph*Vh + Ph*Vl + Pl*Vh ----
#pragma unroll
    for (int ks = 0; ks < 4; ++ks) {
      unsigned ah[4], al[4];
      splitpk(s[2 * ks][0], s[2 * ks][1], ah[0], al[0]);
      splitpk(s[2 * ks][2], s[2 * ks][3], ah[1], al[1]);
      splitpk(s[2 * ks + 1][0], s[2 * ks + 1][1], ah[2], al[2]);
      splitpk(s[2 * ks + 1][2], s[2 * ks + 1][3], ah[3], al[3]);
#pragma unroll
      for (int u = 0; u < 8; ++u) {
        unsigned vh[4], vl[4];
        const unsigned vaddr = smb + SM_VH + (unsigned)(16 * ks + rowVl) * 256u +
                               (unsigned)(((2 * u + cVoff) ^ l7) << 4);
        ldsm4t(vh, vaddr);
        ldsm4t(vl, vaddr + 16384u);
        mma16816(o[2 * u], ah, vh[0], vh[1]);
        mma16816(o[2 * u + 1], ah, vh[2], vh[3]);
        mma16816(o[2 * u], ah, vl[0], vl[1]);
        mma16816(o[2 * u + 1], ah, vl[2], vl[3]);
        mma16816(o[2 * u], al, vh[0], vh[1]);
        mma16816(o[2 * u + 1], al, vh[2], vh[3]);
      }
    }

    if (kt + 1 < kte) {  // all warps past reads -> refill buffer for next tile
      __syncthreads();
      const size_t nk = (size_t)(kt + 1) * BK * HD;
      copy_tile_async(smb + SM_KH, Kh + nk, tid);
      copy_tile_async(smb + SM_KL, Kl + nk, tid);
      copy_tile_async(smb + SM_VH, Vh + nk, tid);
      copy_tile_async(smb + SM_VL, Vl + nk, tid);
      asm volatile("cp.async.commit_group;" ::: "memory");
    }
  }  // kt

  // ---- epilogue: write unnormalized partial O + (m, l) to scratch ----
  const int slot = ((b * 64 + qt) << 2) + c;
  float* op = g_opart[slot];
  const int r0l = 16 * w + quad;
#pragma unroll
  for (int n = 0; n < 16; ++n) {
    const int col = 8 * n + 2 * qlane;
    *(float2*)(op + r0l * HD + col) = make_float2(o[n][0], o[n][1]);
    *(float2*)(op + (r0l + 8) * HD + col) = make_float2(o[n][2], o[n][3]);
  }
  if (qlane == 0) {
    g_mlpart[slot][r0l] = make_float2(m0, l0);
    g_mlpart[slot][r0l + 8] = make_float2(m1, l1);
  }
}

// ---- Pass 3: combine partials (one warp per output row) ----
__global__ __launch_bounds__(256)
void combine_kernel(float* __restrict__ Og) {
  const int row = (blockIdx.x * blockDim.x + threadIdx.x) >> 5;  // 0..16383
  const int lane = threadIdx.x & 31;
  const int b = row >> 12, r = row & 4095;
  const int qt = r >> 6, rr = r & 63;
  const int nc = (qt >> 4) + 1;
  const int slot0 = (b * 64 + qt) << 2;

  float m[4], l[4];
  float mstar = -CUDART_INF_F;
#pragma unroll
  for (int c = 0; c < 4; ++c) {
    if (c < nc) {
      const float2 ml = g_mlpart[slot0 + c][rr];
      m[c] = ml.x;
      l[c] = ml.y;
      mstar = fmaxf(mstar, ml.x);
    }
  }
  float denom = 0.f, wgt[4];
#pragma unroll
  for (int c = 0; c < 4; ++c) {
    if (c < nc) {
      wgt[c] = __expf(m[c] - mstar);
      denom += wgt[c] * l[c];
    }
  }
  float4 acc = make_float4(0.f, 0.f, 0.f, 0.f);
#pragma unroll
  for (int c = 0; c < 4; ++c) {
    if (c < nc) {
      const float4 v = *(const float4*)(g_opart[slot0 + c] + rr * HD + lane * 4);
      acc.x += wgt[c] * v.x;
      acc.y += wgt[c] * v.y;
      acc.z += wgt[c] * v.z;
      acc.w += wgt[c] * v.w;
    }
  }
  const float inv = 1.f / denom;
  acc.x *= inv; acc.y *= inv; acc.z *= inv; acc.w *= inv;
  *(float4*)(Og + ((size_t)b * SEQ + r) * HD + lane * 4) = acc;
}

extern "C" void kernel_launch(void* const* d_in, const int* in_sizes, int n_in,
                              void* d_out, int out_size) {
  const float* K = (const float*)d_in[0];
  const float* Q = (const float*)d_in[1];
  const float* V = (const float*)d_in[2];
  float* O = (float*)d_out;

  cvt_kernel<<<2048, 256>>>(K, Q, V);

  cudaFuncSetAttribute(fa_mma_kernel, cudaFuncAttributeMaxDynamicSharedMemorySize,
                       SMEM_BYTES);
  // chunks per batch: sum over qt of (qt/16+1) = 160; batches interleaved.
  fa_mma_kernel<<<160 * NB, NTH, SMEM_BYTES>>>();

  combine_kernel<<<(NB * SEQ * 32) / 256, 256>>>(O);
}